// round 15
// baseline (speedup 1.0000x reference)
#include <cuda_runtime.h>
#include <cuda_fp16.h>
#include <cstdint>

#define N_NODES 50000
#define E_EDGES 800000
#define D 128
#define NGRAPH 64

#define SCAN_TPB 256
#define SCAN_CHUNK 512
#define SCAN_NBLK ((N_NODES + SCAN_CHUNK - 1) / SCAN_CHUNK)   // 98

// ---------------- scratch (static __device__, no allocation) ----------------
// Invariant: g_dc, g_sums, g_cnt are ZERO at entry to every kernel_launch call.
__device__ __half g_h1[N_NODES * D];    // fp16 H' = dis*(A@W) buffers
__device__ __half g_h2[N_NODES * D];
__device__ __half g_x11[N_NODES * D];   // fp16 layer-1 outputs
__device__ __half g_x12[N_NODES * D];
__device__ __half g_y21[N_NODES * D];   // fp16 layer-2 outputs (pre-pool)
__device__ __half g_y22[N_NODES * D];
__device__ float2 g_dc1[N_NODES];       // (weighted degree w/o self-loop, count)
__device__ float2 g_dc2[N_NODES];
__device__ float  g_dis1[N_NODES];
__device__ float  g_dis2[N_NODES];
__device__ int    g_rp1[N_NODES + 1];
__device__ int    g_rp2[N_NODES + 1];
__device__ int    g_cur1[N_NODES];
__device__ int    g_cur2[N_NODES];
__device__ int2   g_m1[E_EDGES];        // (src, float_bits(ew))
__device__ int2   g_m2[E_EDGES];
__device__ float  g_sums[NGRAPH * D];
__device__ float  g_cnt[NGRAPH];
__device__ int    g_bsum[2][SCAN_NBLK];

// ---------------- helpers ----------------
__device__ __forceinline__ void red_add_v4(float* p, float a, float b, float c, float d) {
    asm volatile(
        "{\n\t"
        ".reg .u64 q;\n\t"
        "cvta.to.global.u64 q, %0;\n\t"
        "red.global.add.v4.f32 [q], {%1, %2, %3, %4};\n\t"
        "}"
        :: "l"(p), "f"(a), "f"(b), "f"(c), "f"(d) : "memory");
}
__device__ __forceinline__ void red_add_v2(float2* p, float a, float b) {
    asm volatile(
        "{\n\t"
        ".reg .u64 q;\n\t"
        "cvta.to.global.u64 q, %0;\n\t"
        "red.global.add.v2.f32 [q], {%1, %2};\n\t"
        "}"
        :: "l"(p), "f"(a), "f"(b) : "memory");
}
__device__ __forceinline__ float4 ldg_h4(const __half* __restrict__ H, int row, int lane) {
    uint2 raw = __ldg((const uint2*)(H + row * 128 + lane * 4));
    __half2 p0 = *reinterpret_cast<__half2*>(&raw.x);
    __half2 p1 = *reinterpret_cast<__half2*>(&raw.y);
    float2 f0 = __half22float2(p0);
    float2 f1 = __half22float2(p1);
    return make_float4(f0.x, f0.y, f1.x, f1.y);
}
__device__ __forceinline__ void st_h4(__half* __restrict__ X, int row, int lane, float4 v) {
    __half2 h0 = __floats2half2_rn(v.x, v.y);
    __half2 h1 = __floats2half2_rn(v.z, v.w);
    uint2 raw;
    raw.x = *reinterpret_cast<uint32_t*>(&h0);
    raw.y = *reinterpret_cast<uint32_t*>(&h1);
    *(uint2*)(X + row * 128 + lane * 4) = raw;
}

// ---------------- CSR build (both graphs per kernel) ----------------

__global__ void k_deg(const int* __restrict__ ei1, const float* __restrict__ ew1,
                      const int* __restrict__ ei2, const float* __restrict__ ew2) {
    int t = blockIdx.x * blockDim.x + threadIdx.x;
    if (t < E_EDGES) {
        red_add_v2(&g_dc1[ei1[E_EDGES + t]], ew1[t], 1.0f);
    } else if (t < 2 * E_EDGES) {
        int e = t - E_EDGES;
        red_add_v2(&g_dc2[ei2[E_EDGES + e]], ew2[e], 1.0f);
    }
}

__global__ __launch_bounds__(SCAN_TPB) void k_scanA() {
    int g = blockIdx.y;
    const float2* dc = g ? g_dc2 : g_dc1;
    int base = blockIdx.x * SCAN_CHUNK;
    int t = threadIdx.x;
    __shared__ int red[SCAN_TPB];
    int s = 0;
    for (int i = t; i < SCAN_CHUNK; i += SCAN_TPB) {
        int idx = base + i;
        if (idx < N_NODES) s += (int)(dc[idx].y + 0.5f);
    }
    red[t] = s;
    __syncthreads();
    for (int off = SCAN_TPB / 2; off > 0; off >>= 1) {
        if (t < off) red[t] += red[t + off];
        __syncthreads();
    }
    if (t == 0) g_bsum[g][blockIdx.x] = red[0];
}

__global__ void k_scanB() {
    int t = threadIdx.x;
    if (t < 2) {
        int* bs = g_bsum[t];
        int run = 0;
        for (int b = 0; b < SCAN_NBLK; b++) {
            int v = bs[b];
            bs[b] = run;
            run += v;
        }
        int* rp = t ? g_rp2 : g_rp1;
        rp[N_NODES] = run;
    }
}

__global__ __launch_bounds__(SCAN_TPB) void k_scanC() {
    int g = blockIdx.y;
    float2* dc = g ? g_dc2 : g_dc1;
    int* rp = g ? g_rp2 : g_rp1;
    int* cur = g ? g_cur2 : g_cur1;
    float* dis = g ? g_dis2 : g_dis1;
    int base = blockIdx.x * SCAN_CHUNK;
    int t = threadIdx.x;

    __shared__ int cnts[SCAN_CHUNK];
    __shared__ int tsum[SCAN_TPB];

    for (int i = t; i < SCAN_CHUNK; i += SCAN_TPB) {
        int idx = base + i;
        if (idx < N_NODES) {
            float2 v = dc[idx];
            cnts[i] = (int)(v.y + 0.5f);
            dis[idx] = rsqrtf(v.x + 1.0f);     // +1 self-loop
            dc[idx] = make_float2(0.f, 0.f);   // restore zero-invariant
        } else {
            cnts[i] = 0;
        }
    }
    __syncthreads();

    const int EPT = SCAN_CHUNK / SCAN_TPB;     // 2
    int e0 = t * EPT;
    int ls = 0;
#pragma unroll
    for (int i = 0; i < EPT; i++) ls += cnts[e0 + i];
    tsum[t] = ls;
    __syncthreads();

    for (int off = 1; off < SCAN_TPB; off <<= 1) {
        int v = (t >= off) ? tsum[t - off] : 0;
        __syncthreads();
        tsum[t] += v;
        __syncthreads();
    }
    int run = g_bsum[g][blockIdx.x] + (t ? tsum[t - 1] : 0);

#pragma unroll
    for (int i = 0; i < EPT; i++) {
        int idx = base + e0 + i;
        if (idx < N_NODES) {
            rp[idx] = run;
            cur[idx] = run;
            run += cnts[e0 + i];
        }
    }
}

__global__ void k_fill(const int* __restrict__ ei1, const float* __restrict__ ew1,
                       const int* __restrict__ ei2, const float* __restrict__ ew2) {
    int t = blockIdx.x * blockDim.x + threadIdx.x;
    if (t < E_EDGES) {
        int s = ei1[t], d = ei1[E_EDGES + t];
        int pos = atomicAdd(&g_cur1[d], 1);
        g_m1[pos] = make_int2(s, __float_as_int(ew1[t]));
    } else if (t < 2 * E_EDGES) {
        int e = t - E_EDGES;
        int s = ei2[e], d = ei2[E_EDGES + e];
        int pos = atomicAdd(&g_cur2[d], 1);
        g_m2[pos] = make_int2(s, __float_as_int(ew2[e]));
    }
}

// -------- tensor-core GEMM (A fp32): C[N,128](fp16) = dis[r] * (A @ W) --------
__global__ __launch_bounds__(256) void k_gemm_tc(
    const float* __restrict__ A, const float* __restrict__ W,
    const float* __restrict__ dis, __half* __restrict__ C) {
    __shared__ __half Wt[128][136];

    int t = threadIdx.x;
    for (int i = t; i < 128 * 128; i += 256) {
        int k = i >> 7, n = i & 127;
        Wt[n][k] = __float2half_rn(W[i]);
    }
    __syncthreads();

    int w = t >> 5;
    int lane = t & 31;
    int g = lane >> 2;
    int tq = lane & 3;
    int r0 = blockIdx.x * 128 + w * 16 + g;
    int r1 = r0 + 8;
    bool ok0 = r0 < N_NODES, ok1 = r1 < N_NODES;
    float ds0 = ok0 ? dis[r0] : 0.f;
    float ds1 = ok1 ? dis[r1] : 0.f;

    uint32_t af[8][4];
#pragma unroll
    for (int ks = 0; ks < 8; ks++) {
        int c = ks * 16 + tq * 2;
        float2 z = make_float2(0.f, 0.f);
        float2 f0 = ok0 ? *(const float2*)(A + r0 * 128 + c) : z;
        float2 f1 = ok1 ? *(const float2*)(A + r1 * 128 + c) : z;
        float2 f2 = ok0 ? *(const float2*)(A + r0 * 128 + c + 8) : z;
        float2 f3 = ok1 ? *(const float2*)(A + r1 * 128 + c + 8) : z;
        __half2 h0 = __floats2half2_rn(f0.x, f0.y);
        __half2 h1 = __floats2half2_rn(f1.x, f1.y);
        __half2 h2 = __floats2half2_rn(f2.x, f2.y);
        __half2 h3 = __floats2half2_rn(f3.x, f3.y);
        af[ks][0] = *reinterpret_cast<uint32_t*>(&h0);
        af[ks][1] = *reinterpret_cast<uint32_t*>(&h1);
        af[ks][2] = *reinterpret_cast<uint32_t*>(&h2);
        af[ks][3] = *reinterpret_cast<uint32_t*>(&h3);
    }

#pragma unroll
    for (int nt = 0; nt < 16; nt++) {
        float c0 = 0.f, c1 = 0.f, c2 = 0.f, c3 = 0.f;
        int n = nt * 8 + g;
        const __half* wrow = &Wt[n][0];
#pragma unroll
        for (int ks = 0; ks < 8; ks++) {
            uint32_t b0 = *(const uint32_t*)(wrow + ks * 16 + tq * 2);
            uint32_t b1 = *(const uint32_t*)(wrow + ks * 16 + tq * 2 + 8);
            asm volatile(
                "mma.sync.aligned.m16n8k16.row.col.f32.f16.f16.f32 "
                "{%0,%1,%2,%3}, {%4,%5,%6,%7}, {%8,%9}, {%0,%1,%2,%3};\n"
                : "+f"(c0), "+f"(c1), "+f"(c2), "+f"(c3)
                : "r"(af[ks][0]), "r"(af[ks][1]), "r"(af[ks][2]), "r"(af[ks][3]),
                  "r"(b0), "r"(b1));
        }
        int col = nt * 8 + tq * 2;
        if (ok0) {
            __half2 h = __floats2half2_rn(ds0 * c0, ds0 * c1);
            *(uint32_t*)(C + r0 * 128 + col) = *reinterpret_cast<uint32_t*>(&h);
        }
        if (ok1) {
            __half2 h = __floats2half2_rn(ds1 * c2, ds1 * c3);
            *(uint32_t*)(C + r1 * 128 + col) = *reinterpret_cast<uint32_t*>(&h);
        }
    }
}

// -------- tensor-core GEMM (A fp16): C[N,128](fp16) = dis[r] * (A @ W) --------
__global__ __launch_bounds__(256) void k_gemm_tc_h(
    const __half* __restrict__ A, const float* __restrict__ W,
    const float* __restrict__ dis, __half* __restrict__ C) {
    __shared__ __half Wt[128][136];

    int t = threadIdx.x;
    for (int i = t; i < 128 * 128; i += 256) {
        int k = i >> 7, n = i & 127;
        Wt[n][k] = __float2half_rn(W[i]);
    }
    __syncthreads();

    int w = t >> 5;
    int lane = t & 31;
    int g = lane >> 2;
    int tq = lane & 3;
    int r0 = blockIdx.x * 128 + w * 16 + g;
    int r1 = r0 + 8;
    bool ok0 = r0 < N_NODES, ok1 = r1 < N_NODES;
    float ds0 = ok0 ? dis[r0] : 0.f;
    float ds1 = ok1 ? dis[r1] : 0.f;

    uint32_t af[8][4];
#pragma unroll
    for (int ks = 0; ks < 8; ks++) {
        int c = ks * 16 + tq * 2;
        af[ks][0] = ok0 ? *(const uint32_t*)(A + r0 * 128 + c) : 0u;
        af[ks][1] = ok1 ? *(const uint32_t*)(A + r1 * 128 + c) : 0u;
        af[ks][2] = ok0 ? *(const uint32_t*)(A + r0 * 128 + c + 8) : 0u;
        af[ks][3] = ok1 ? *(const uint32_t*)(A + r1 * 128 + c + 8) : 0u;
    }

#pragma unroll
    for (int nt = 0; nt < 16; nt++) {
        float c0 = 0.f, c1 = 0.f, c2 = 0.f, c3 = 0.f;
        int n = nt * 8 + g;
        const __half* wrow = &Wt[n][0];
#pragma unroll
        for (int ks = 0; ks < 8; ks++) {
            uint32_t b0 = *(const uint32_t*)(wrow + ks * 16 + tq * 2);
            uint32_t b1 = *(const uint32_t*)(wrow + ks * 16 + tq * 2 + 8);
            asm volatile(
                "mma.sync.aligned.m16n8k16.row.col.f32.f16.f16.f32 "
                "{%0,%1,%2,%3}, {%4,%5,%6,%7}, {%8,%9}, {%0,%1,%2,%3};\n"
                : "+f"(c0), "+f"(c1), "+f"(c2), "+f"(c3)
                : "r"(af[ks][0]), "r"(af[ks][1]), "r"(af[ks][2]), "r"(af[ks][3]),
                  "r"(b0), "r"(b1));
        }
        int col = nt * 8 + tq * 2;
        if (ok0) {
            __half2 h = __floats2half2_rn(ds0 * c0, ds0 * c1);
            *(uint32_t*)(C + r0 * 128 + col) = *reinterpret_cast<uint32_t*>(&h);
        }
        if (ok1) {
            __half2 h = __floats2half2_rn(ds1 * c2, ds1 * c3);
            *(uint32_t*)(C + r1 * 128 + col) = *reinterpret_cast<uint32_t*>(&h);
        }
    }
}

// --------- aggregation body: acc = H'[d] + Σ ew·H'[s]; X = dis[d]*acc + b ------
__device__ __forceinline__ float4 agg_node(
    const __half* __restrict__ H, const int* __restrict__ rp,
    const int2* __restrict__ meta, const float* __restrict__ dis,
    int d, int lane, float4 bv) {
    int beg = rp[d], end = rp[d + 1];
    float4 acc = ldg_h4(H, d, lane);            // self-loop term H'[d]

    for (int base = beg; base < end; base += 32) {
        int2 mm = make_int2(0, 0);
        if (base + lane < end) mm = __ldg(&meta[base + lane]);
        int m = min(32, end - base);
        int j = 0;
        for (; j + 4 <= m; j += 4) {
            int s0 = __shfl_sync(0xffffffffu, mm.x, j);
            int s1 = __shfl_sync(0xffffffffu, mm.x, j + 1);
            int s2 = __shfl_sync(0xffffffffu, mm.x, j + 2);
            int s3 = __shfl_sync(0xffffffffu, mm.x, j + 3);
            float w0 = __int_as_float(__shfl_sync(0xffffffffu, mm.y, j));
            float w1 = __int_as_float(__shfl_sync(0xffffffffu, mm.y, j + 1));
            float w2 = __int_as_float(__shfl_sync(0xffffffffu, mm.y, j + 2));
            float w3 = __int_as_float(__shfl_sync(0xffffffffu, mm.y, j + 3));
            float4 v0 = ldg_h4(H, s0, lane);
            float4 v1 = ldg_h4(H, s1, lane);
            float4 v2 = ldg_h4(H, s2, lane);
            float4 v3 = ldg_h4(H, s3, lane);
            acc.x = fmaf(w0, v0.x, fmaf(w1, v1.x, fmaf(w2, v2.x, fmaf(w3, v3.x, acc.x))));
            acc.y = fmaf(w0, v0.y, fmaf(w1, v1.y, fmaf(w2, v2.y, fmaf(w3, v3.y, acc.y))));
            acc.z = fmaf(w0, v0.z, fmaf(w1, v1.z, fmaf(w2, v2.z, fmaf(w3, v3.z, acc.z))));
            acc.w = fmaf(w0, v0.w, fmaf(w1, v1.w, fmaf(w2, v2.w, fmaf(w3, v3.w, acc.w))));
        }
        for (; j < m; j++) {
            int s = __shfl_sync(0xffffffffu, mm.x, j);
            float w = __int_as_float(__shfl_sync(0xffffffffu, mm.y, j));
            float4 v = ldg_h4(H, s, lane);
            acc.x = fmaf(w, v.x, acc.x); acc.y = fmaf(w, v.y, acc.y);
            acc.z = fmaf(w, v.z, acc.z); acc.w = fmaf(w, v.w, acc.w);
        }
    }
    float ds = dis[d];
    return make_float4(fmaf(ds, acc.x, bv.x), fmaf(ds, acc.y, bv.y),
                       fmaf(ds, acc.z, bv.z), fmaf(ds, acc.w, bv.w));
}

// GCN aggregation layer (used for BOTH layers), one graph, warp per node
__global__ __launch_bounds__(256) void k_agg1g(
    const __half* __restrict__ H, __half* __restrict__ X,
    const float* __restrict__ bias,
    const int* __restrict__ rp, const int2* __restrict__ meta,
    const float* __restrict__ dis) {
    int d = (blockIdx.x * blockDim.x + threadIdx.x) >> 5;
    int lane = threadIdx.x & 31;
    if (d >= N_NODES) return;
    float4 bv = *(const float4*)(bias + lane * 4);
    float4 acc = agg_node(H, rp, meta, dis, d, lane, bv);
    st_h4(X, d, lane, acc);
}

// streaming pool: x = (x12-x11)*(y22-y21), reduce into per-graph sums
__global__ __launch_bounds__(256) void k_pool(const int* __restrict__ batch) {
    int t = blockIdx.x * blockDim.x + threadIdx.x;    // one thread per 4 channels
    if (t >= N_NODES * 32) return;
    int d = t >> 5;
    int lane = t & 31;
    float4 a11 = ldg_h4(g_x11, d, lane);
    float4 a12 = ldg_h4(g_x12, d, lane);
    float4 a21 = ldg_h4(g_y21, d, lane);
    float4 a22 = ldg_h4(g_y22, d, lane);
    float px = (a12.x - a11.x) * (a22.x - a21.x);
    float py = (a12.y - a11.y) * (a22.y - a21.y);
    float pz = (a12.z - a11.z) * (a22.z - a21.z);
    float pw = (a12.w - a11.w) * (a22.w - a21.w);
    int gph = __ldg(&batch[d]);
    red_add_v4(g_sums + gph * 128 + lane * 4, px, py, pz, pw);
    if (lane == 0) atomicAdd(&g_cnt[gph], 1.0f);
}

// ---------------- final MLP (self-cleans g_sums / g_cnt) ----------------
__global__ __launch_bounds__(128) void k_mlp(
    const float* __restrict__ M1w, const float* __restrict__ M1b,
    const float* __restrict__ M2w, const float* __restrict__ M2b,
    const float* __restrict__ M3w, const float* __restrict__ M3b,
    const float* __restrict__ M4w, const float* __restrict__ M4b,
    float* __restrict__ out) {
    __shared__ float gv[128], h1s[128], h2s[64], h3s[32];
    int g = blockIdx.x;
    int t = threadIdx.x;
    float cnt = fmaxf(g_cnt[g], 1.0f);
    gv[t] = g_sums[g * 128 + t] / cnt;
    __syncthreads();
    g_sums[g * 128 + t] = 0.0f;
    if (t == 0) g_cnt[g] = 0.0f;
    float acc = M1b[t];
#pragma unroll 8
    for (int c = 0; c < 128; c++) acc += gv[c] * M1w[c * 128 + t];
    h1s[t] = acc;
    __syncthreads();
    if (t < 64) {
        acc = M2b[t];
#pragma unroll 8
        for (int c = 0; c < 128; c++) acc += h1s[c] * M2w[c * 64 + t];
        h2s[t] = acc;
    }
    __syncthreads();
    if (t < 32) {
        acc = M3b[t];
#pragma unroll 8
        for (int c = 0; c < 64; c++) acc += h2s[c] * M3w[c * 32 + t];
        h3s[t] = acc;
    }
    __syncthreads();
    if (t < 32) {
        float v = h3s[t] * M4w[t];
#pragma unroll
        for (int off = 16; off > 0; off >>= 1)
            v += __shfl_down_sync(0xffffffff, v, off);
        if (t == 0) out[g] = v + M4b[0];
    }
}

// ---------------- launch ----------------
extern "C" void kernel_launch(void* const* d_in, const int* in_sizes, int n_in,
                              void* d_out, int out_size) {
    const int*   ei1  = (const int*)d_in[0];
    const float* ew1  = (const float*)d_in[1];
    const int*   ei2  = (const int*)d_in[2];
    const float* ew2  = (const float*)d_in[3];
    const float* fm0  = (const float*)d_in[4];
    const float* fm1  = (const float*)d_in[5];
    const int*   batch = (const int*)d_in[6];
    const float* W1  = (const float*)d_in[7];
    const float* b1  = (const float*)d_in[8];
    const float* W2  = (const float*)d_in[9];
    const float* b2  = (const float*)d_in[10];
    const float* M1w = (const float*)d_in[11];
    const float* M1b = (const float*)d_in[12];
    const float* M2w = (const float*)d_in[13];
    const float* M2b = (const float*)d_in[14];
    const float* M3w = (const float*)d_in[15];
    const float* M3b = (const float*)d_in[16];
    const float* M4w = (const float*)d_in[17];
    const float* M4b = (const float*)d_in[18];
    float* out = (float*)d_out;

    void *p_h1, *p_h2, *p_x11, *p_x12, *p_y21, *p_y22;
    void *p_rp1, *p_rp2, *p_m1, *p_m2, *p_dis1, *p_dis2;
    cudaGetSymbolAddress(&p_h1, g_h1);
    cudaGetSymbolAddress(&p_h2, g_h2);
    cudaGetSymbolAddress(&p_x11, g_x11);
    cudaGetSymbolAddress(&p_x12, g_x12);
    cudaGetSymbolAddress(&p_y21, g_y21);
    cudaGetSymbolAddress(&p_y22, g_y22);
    cudaGetSymbolAddress(&p_rp1, g_rp1);
    cudaGetSymbolAddress(&p_rp2, g_rp2);
    cudaGetSymbolAddress(&p_m1, g_m1);
    cudaGetSymbolAddress(&p_m2, g_m2);
    cudaGetSymbolAddress(&p_dis1, g_dis1);
    cudaGetSymbolAddress(&p_dis2, g_dis2);
    __half* h1 = (__half*)p_h1;   __half* h2 = (__half*)p_h2;
    __half* x11 = (__half*)p_x11; __half* x12 = (__half*)p_x12;
    __half* y21 = (__half*)p_y21; __half* y22 = (__half*)p_y22;
    const float* dis1 = (const float*)p_dis1;
    const float* dis2 = (const float*)p_dis2;

    static cudaStream_t sA = nullptr, sB = nullptr;
    static cudaEvent_t eScan = nullptr, eFill = nullptr, eA = nullptr, eB = nullptr;
    if (sA == nullptr) {
        cudaStreamCreateWithFlags(&sA, cudaStreamNonBlocking);
        cudaStreamCreateWithFlags(&sB, cudaStreamNonBlocking);
        cudaEventCreateWithFlags(&eScan, cudaEventDisableTiming);
        cudaEventCreateWithFlags(&eFill, cudaEventDisableTiming);
        cudaEventCreateWithFlags(&eA, cudaEventDisableTiming);
        cudaEventCreateWithFlags(&eB, cudaEventDisableTiming);
    }

    const int TPB = 256;
    int edgeBlocks = (2 * E_EDGES + TPB - 1) / TPB;
    int gemmBlocks = (N_NODES + 127) / 128;
    int aggBlocks  = (N_NODES * 32 + TPB - 1) / TPB;
    int poolBlocks = (N_NODES * 32 + TPB - 1) / TPB;

    // CSR head: deg -> scan (produces dis + rp + cur)
    k_deg<<<edgeBlocks, TPB>>>(ei1, ew1, ei2, ew2);
    {
        dim3 sg(SCAN_NBLK, 2);
        k_scanA<<<sg, SCAN_TPB>>>();
        k_scanB<<<1, 32>>>();
        k_scanC<<<sg, SCAN_TPB>>>();
    }
    cudaEventRecord(eScan, 0);

    // gemm1 on streams (needs dis), concurrent with fill on default stream
    cudaStreamWaitEvent(sA, eScan, 0);
    cudaStreamWaitEvent(sB, eScan, 0);
    k_gemm_tc<<<gemmBlocks, TPB, 0, sA>>>(fm0, W1, dis1, h1);
    k_gemm_tc<<<gemmBlocks, TPB, 0, sB>>>(fm1, W1, dis2, h2);

    k_fill<<<edgeBlocks, TPB>>>(ei1, ew1, ei2, ew2);
    cudaEventRecord(eFill, 0);
    cudaStreamWaitEvent(sA, eFill, 0);
    cudaStreamWaitEvent(sB, eFill, 0);

    // full per-graph pipelines: agg1 -> gemm2 -> agg2 (gemm hides under the
    // other stream's L2-bound aggregation)
    k_agg1g<<<aggBlocks, TPB, 0, sA>>>(h1, x11, b1, (const int*)p_rp1,
                                       (const int2*)p_m1, dis1);
    k_gemm_tc_h<<<gemmBlocks, TPB, 0, sA>>>(x11, W2, dis1, h1);
    k_agg1g<<<aggBlocks, TPB, 0, sA>>>(h1, y21, b2, (const int*)p_rp1,
                                       (const int2*)p_m1, dis1);
    cudaEventRecord(eA, sA);

    k_agg1g<<<aggBlocks, TPB, 0, sB>>>(h2, x12, b1, (const int*)p_rp2,
                                       (const int2*)p_m2, dis2);
    k_gemm_tc_h<<<gemmBlocks, TPB, 0, sB>>>(x12, W2, dis2, h2);
    k_agg1g<<<aggBlocks, TPB, 0, sB>>>(h2, y22, b2, (const int*)p_rp2,
                                       (const int2*)p_m2, dis2);
    cudaEventRecord(eB, sB);

    cudaStreamWaitEvent(0, eA, 0);
    cudaStreamWaitEvent(0, eB, 0);

    // join: streaming pool + MLP
    k_pool<<<poolBlocks, TPB>>>(batch);
    k_mlp<<<NGRAPH, 128>>>(M1w, M1b, M2w, M2b, M3w, M3b, M4w, M4b, out);
}

// round 16
// speedup vs baseline: 1.1012x; 1.1012x over previous
#include <cuda_runtime.h>
#include <cuda_fp16.h>
#include <cstdint>

#define N_NODES 50000
#define E_EDGES 800000
#define D 128
#define NGRAPH 64

#define SCAN_TPB 256
#define SCAN_CHUNK 512
#define SCAN_NBLK ((N_NODES + SCAN_CHUNK - 1) / SCAN_CHUNK)   // 98

// ---------------- scratch (static __device__, no allocation) ----------------
// Invariant: g_dc, g_sums, g_cnt are ZERO at entry to every kernel_launch call.
__device__ __half g_h1[N_NODES * D];    // fp16 H' = dis*(A@W) buffers
__device__ __half g_h2[N_NODES * D];
__device__ __half g_x11[N_NODES * D];   // fp16 layer-1 outputs
__device__ __half g_x12[N_NODES * D];
__device__ float2 g_dc1[N_NODES];       // (weighted degree w/o self-loop, count)
__device__ float2 g_dc2[N_NODES];
__device__ float  g_dis1[N_NODES];
__device__ float  g_dis2[N_NODES];
__device__ int    g_rp1[N_NODES + 1];
__device__ int    g_rp2[N_NODES + 1];
__device__ int    g_cur1[N_NODES];
__device__ int    g_cur2[N_NODES];
__device__ int2   g_m1[E_EDGES];        // (src, float_bits(ew))
__device__ int2   g_m2[E_EDGES];
__device__ float  g_sums[NGRAPH * D];
__device__ float  g_cnt[NGRAPH];
__device__ int    g_bsum[2][SCAN_NBLK];

// ---------------- helpers ----------------
__device__ __forceinline__ void red_add_v4(float* p, float a, float b, float c, float d) {
    asm volatile(
        "{\n\t"
        ".reg .u64 q;\n\t"
        "cvta.to.global.u64 q, %0;\n\t"
        "red.global.add.v4.f32 [q], {%1, %2, %3, %4};\n\t"
        "}"
        :: "l"(p), "f"(a), "f"(b), "f"(c), "f"(d) : "memory");
}
__device__ __forceinline__ void red_add_v2(float2* p, float a, float b) {
    asm volatile(
        "{\n\t"
        ".reg .u64 q;\n\t"
        "cvta.to.global.u64 q, %0;\n\t"
        "red.global.add.v2.f32 [q], {%1, %2};\n\t"
        "}"
        :: "l"(p), "f"(a), "f"(b) : "memory");
}
__device__ __forceinline__ float4 ldg_h4(const __half* __restrict__ H, int row, int lane) {
    uint2 raw = __ldg((const uint2*)(H + row * 128 + lane * 4));
    __half2 p0 = *reinterpret_cast<__half2*>(&raw.x);
    __half2 p1 = *reinterpret_cast<__half2*>(&raw.y);
    float2 f0 = __half22float2(p0);
    float2 f1 = __half22float2(p1);
    return make_float4(f0.x, f0.y, f1.x, f1.y);
}
__device__ __forceinline__ void st_h4(__half* __restrict__ X, int row, int lane, float4 v) {
    __half2 h0 = __floats2half2_rn(v.x, v.y);
    __half2 h1 = __floats2half2_rn(v.z, v.w);
    uint2 raw;
    raw.x = *reinterpret_cast<uint32_t*>(&h0);
    raw.y = *reinterpret_cast<uint32_t*>(&h1);
    *(uint2*)(X + row * 128 + lane * 4) = raw;
}

// ---------------- CSR build (both graphs per kernel) ----------------

__global__ void k_deg(const int* __restrict__ ei1, const float* __restrict__ ew1,
                      const int* __restrict__ ei2, const float* __restrict__ ew2) {
    int t = blockIdx.x * blockDim.x + threadIdx.x;
    if (t < E_EDGES) {
        red_add_v2(&g_dc1[ei1[E_EDGES + t]], ew1[t], 1.0f);
    } else if (t < 2 * E_EDGES) {
        int e = t - E_EDGES;
        red_add_v2(&g_dc2[ei2[E_EDGES + e]], ew2[e], 1.0f);
    }
}

// tiny coalesced dis kernel — unblocks gemm1 without waiting for the scans.
// Does NOT touch dc (scanC still needs the counts and re-zeroes it).
__global__ void k_dis() {
    int i = blockIdx.x * blockDim.x + threadIdx.x;
    if (i < N_NODES) {
        g_dis1[i] = rsqrtf(g_dc1[i].x + 1.0f);   // +1 self-loop
        g_dis2[i] = rsqrtf(g_dc2[i].x + 1.0f);
    }
}

__global__ __launch_bounds__(SCAN_TPB) void k_scanA() {
    int g = blockIdx.y;
    const float2* dc = g ? g_dc2 : g_dc1;
    int base = blockIdx.x * SCAN_CHUNK;
    int t = threadIdx.x;
    __shared__ int red[SCAN_TPB];
    int s = 0;
    for (int i = t; i < SCAN_CHUNK; i += SCAN_TPB) {
        int idx = base + i;
        if (idx < N_NODES) s += (int)(dc[idx].y + 0.5f);
    }
    red[t] = s;
    __syncthreads();
    for (int off = SCAN_TPB / 2; off > 0; off >>= 1) {
        if (t < off) red[t] += red[t + off];
        __syncthreads();
    }
    if (t == 0) g_bsum[g][blockIdx.x] = red[0];
}

__global__ void k_scanB() {
    int t = threadIdx.x;
    if (t < 2) {
        int* bs = g_bsum[t];
        int run = 0;
        for (int b = 0; b < SCAN_NBLK; b++) {
            int v = bs[b];
            bs[b] = run;
            run += v;
        }
        int* rp = t ? g_rp2 : g_rp1;
        rp[N_NODES] = run;
    }
}

__global__ __launch_bounds__(SCAN_TPB) void k_scanC() {
    int g = blockIdx.y;
    float2* dc = g ? g_dc2 : g_dc1;
    int* rp = g ? g_rp2 : g_rp1;
    int* cur = g ? g_cur2 : g_cur1;
    int base = blockIdx.x * SCAN_CHUNK;
    int t = threadIdx.x;

    __shared__ int cnts[SCAN_CHUNK];
    __shared__ int tsum[SCAN_TPB];

    for (int i = t; i < SCAN_CHUNK; i += SCAN_TPB) {
        int idx = base + i;
        if (idx < N_NODES) {
            float2 v = dc[idx];
            cnts[i] = (int)(v.y + 0.5f);
            dc[idx] = make_float2(0.f, 0.f);   // restore zero-invariant
        } else {
            cnts[i] = 0;
        }
    }
    __syncthreads();

    const int EPT = SCAN_CHUNK / SCAN_TPB;     // 2
    int e0 = t * EPT;
    int ls = 0;
#pragma unroll
    for (int i = 0; i < EPT; i++) ls += cnts[e0 + i];
    tsum[t] = ls;
    __syncthreads();

    for (int off = 1; off < SCAN_TPB; off <<= 1) {
        int v = (t >= off) ? tsum[t - off] : 0;
        __syncthreads();
        tsum[t] += v;
        __syncthreads();
    }
    int run = g_bsum[g][blockIdx.x] + (t ? tsum[t - 1] : 0);

#pragma unroll
    for (int i = 0; i < EPT; i++) {
        int idx = base + e0 + i;
        if (idx < N_NODES) {
            rp[idx] = run;
            cur[idx] = run;
            run += cnts[e0 + i];
        }
    }
}

__global__ void k_fill(const int* __restrict__ ei1, const float* __restrict__ ew1,
                       const int* __restrict__ ei2, const float* __restrict__ ew2) {
    int t = blockIdx.x * blockDim.x + threadIdx.x;
    if (t < E_EDGES) {
        int s = ei1[t], d = ei1[E_EDGES + t];
        int pos = atomicAdd(&g_cur1[d], 1);
        g_m1[pos] = make_int2(s, __float_as_int(ew1[t]));
    } else if (t < 2 * E_EDGES) {
        int e = t - E_EDGES;
        int s = ei2[e], d = ei2[E_EDGES + e];
        int pos = atomicAdd(&g_cur2[d], 1);
        g_m2[pos] = make_int2(s, __float_as_int(ew2[e]));
    }
}

// -------- tensor-core GEMM (A fp32): C[N,128](fp16) = dis[r] * (A @ W) --------
__global__ __launch_bounds__(256) void k_gemm_tc(
    const float* __restrict__ A, const float* __restrict__ W,
    const float* __restrict__ dis, __half* __restrict__ C) {
    __shared__ __half Wt[128][136];

    int t = threadIdx.x;
    for (int i = t; i < 128 * 128; i += 256) {
        int k = i >> 7, n = i & 127;
        Wt[n][k] = __float2half_rn(W[i]);
    }
    __syncthreads();

    int w = t >> 5;
    int lane = t & 31;
    int g = lane >> 2;
    int tq = lane & 3;
    int r0 = blockIdx.x * 128 + w * 16 + g;
    int r1 = r0 + 8;
    bool ok0 = r0 < N_NODES, ok1 = r1 < N_NODES;
    float ds0 = ok0 ? dis[r0] : 0.f;
    float ds1 = ok1 ? dis[r1] : 0.f;

    uint32_t af[8][4];
#pragma unroll
    for (int ks = 0; ks < 8; ks++) {
        int c = ks * 16 + tq * 2;
        float2 z = make_float2(0.f, 0.f);
        float2 f0 = ok0 ? *(const float2*)(A + r0 * 128 + c) : z;
        float2 f1 = ok1 ? *(const float2*)(A + r1 * 128 + c) : z;
        float2 f2 = ok0 ? *(const float2*)(A + r0 * 128 + c + 8) : z;
        float2 f3 = ok1 ? *(const float2*)(A + r1 * 128 + c + 8) : z;
        __half2 h0 = __floats2half2_rn(f0.x, f0.y);
        __half2 h1 = __floats2half2_rn(f1.x, f1.y);
        __half2 h2 = __floats2half2_rn(f2.x, f2.y);
        __half2 h3 = __floats2half2_rn(f3.x, f3.y);
        af[ks][0] = *reinterpret_cast<uint32_t*>(&h0);
        af[ks][1] = *reinterpret_cast<uint32_t*>(&h1);
        af[ks][2] = *reinterpret_cast<uint32_t*>(&h2);
        af[ks][3] = *reinterpret_cast<uint32_t*>(&h3);
    }

#pragma unroll
    for (int nt = 0; nt < 16; nt++) {
        float c0 = 0.f, c1 = 0.f, c2 = 0.f, c3 = 0.f;
        int n = nt * 8 + g;
        const __half* wrow = &Wt[n][0];
#pragma unroll
        for (int ks = 0; ks < 8; ks++) {
            uint32_t b0 = *(const uint32_t*)(wrow + ks * 16 + tq * 2);
            uint32_t b1 = *(const uint32_t*)(wrow + ks * 16 + tq * 2 + 8);
            asm volatile(
                "mma.sync.aligned.m16n8k16.row.col.f32.f16.f16.f32 "
                "{%0,%1,%2,%3}, {%4,%5,%6,%7}, {%8,%9}, {%0,%1,%2,%3};\n"
                : "+f"(c0), "+f"(c1), "+f"(c2), "+f"(c3)
                : "r"(af[ks][0]), "r"(af[ks][1]), "r"(af[ks][2]), "r"(af[ks][3]),
                  "r"(b0), "r"(b1));
        }
        int col = nt * 8 + tq * 2;
        if (ok0) {
            __half2 h = __floats2half2_rn(ds0 * c0, ds0 * c1);
            *(uint32_t*)(C + r0 * 128 + col) = *reinterpret_cast<uint32_t*>(&h);
        }
        if (ok1) {
            __half2 h = __floats2half2_rn(ds1 * c2, ds1 * c3);
            *(uint32_t*)(C + r1 * 128 + col) = *reinterpret_cast<uint32_t*>(&h);
        }
    }
}

// -------- tensor-core GEMM (A fp16): C[N,128](fp16) = dis[r] * (A @ W) --------
__global__ __launch_bounds__(256) void k_gemm_tc_h(
    const __half* __restrict__ A, const float* __restrict__ W,
    const float* __restrict__ dis, __half* __restrict__ C) {
    __shared__ __half Wt[128][136];

    int t = threadIdx.x;
    for (int i = t; i < 128 * 128; i += 256) {
        int k = i >> 7, n = i & 127;
        Wt[n][k] = __float2half_rn(W[i]);
    }
    __syncthreads();

    int w = t >> 5;
    int lane = t & 31;
    int g = lane >> 2;
    int tq = lane & 3;
    int r0 = blockIdx.x * 128 + w * 16 + g;
    int r1 = r0 + 8;
    bool ok0 = r0 < N_NODES, ok1 = r1 < N_NODES;
    float ds0 = ok0 ? dis[r0] : 0.f;
    float ds1 = ok1 ? dis[r1] : 0.f;

    uint32_t af[8][4];
#pragma unroll
    for (int ks = 0; ks < 8; ks++) {
        int c = ks * 16 + tq * 2;
        af[ks][0] = ok0 ? *(const uint32_t*)(A + r0 * 128 + c) : 0u;
        af[ks][1] = ok1 ? *(const uint32_t*)(A + r1 * 128 + c) : 0u;
        af[ks][2] = ok0 ? *(const uint32_t*)(A + r0 * 128 + c + 8) : 0u;
        af[ks][3] = ok1 ? *(const uint32_t*)(A + r1 * 128 + c + 8) : 0u;
    }

#pragma unroll
    for (int nt = 0; nt < 16; nt++) {
        float c0 = 0.f, c1 = 0.f, c2 = 0.f, c3 = 0.f;
        int n = nt * 8 + g;
        const __half* wrow = &Wt[n][0];
#pragma unroll
        for (int ks = 0; ks < 8; ks++) {
            uint32_t b0 = *(const uint32_t*)(wrow + ks * 16 + tq * 2);
            uint32_t b1 = *(const uint32_t*)(wrow + ks * 16 + tq * 2 + 8);
            asm volatile(
                "mma.sync.aligned.m16n8k16.row.col.f32.f16.f16.f32 "
                "{%0,%1,%2,%3}, {%4,%5,%6,%7}, {%8,%9}, {%0,%1,%2,%3};\n"
                : "+f"(c0), "+f"(c1), "+f"(c2), "+f"(c3)
                : "r"(af[ks][0]), "r"(af[ks][1]), "r"(af[ks][2]), "r"(af[ks][3]),
                  "r"(b0), "r"(b1));
        }
        int col = nt * 8 + tq * 2;
        if (ok0) {
            __half2 h = __floats2half2_rn(ds0 * c0, ds0 * c1);
            *(uint32_t*)(C + r0 * 128 + col) = *reinterpret_cast<uint32_t*>(&h);
        }
        if (ok1) {
            __half2 h = __floats2half2_rn(ds1 * c2, ds1 * c3);
            *(uint32_t*)(C + r1 * 128 + col) = *reinterpret_cast<uint32_t*>(&h);
        }
    }
}

// --------- aggregation body: acc = H'[d] + Σ ew·H'[s]; X = dis[d]*acc + b ------
__device__ __forceinline__ float4 agg_node(
    const __half* __restrict__ H, const int* __restrict__ rp,
    const int2* __restrict__ meta, const float* __restrict__ dis,
    int d, int lane, float4 bv) {
    int beg = rp[d], end = rp[d + 1];
    float4 acc = ldg_h4(H, d, lane);            // self-loop term H'[d]

    for (int base = beg; base < end; base += 32) {
        int2 mm = make_int2(0, 0);
        if (base + lane < end) mm = __ldg(&meta[base + lane]);
        int m = min(32, end - base);
        int j = 0;
        for (; j + 4 <= m; j += 4) {
            int s0 = __shfl_sync(0xffffffffu, mm.x, j);
            int s1 = __shfl_sync(0xffffffffu, mm.x, j + 1);
            int s2 = __shfl_sync(0xffffffffu, mm.x, j + 2);
            int s3 = __shfl_sync(0xffffffffu, mm.x, j + 3);
            float w0 = __int_as_float(__shfl_sync(0xffffffffu, mm.y, j));
            float w1 = __int_as_float(__shfl_sync(0xffffffffu, mm.y, j + 1));
            float w2 = __int_as_float(__shfl_sync(0xffffffffu, mm.y, j + 2));
            float w3 = __int_as_float(__shfl_sync(0xffffffffu, mm.y, j + 3));
            float4 v0 = ldg_h4(H, s0, lane);
            float4 v1 = ldg_h4(H, s1, lane);
            float4 v2 = ldg_h4(H, s2, lane);
            float4 v3 = ldg_h4(H, s3, lane);
            acc.x = fmaf(w0, v0.x, fmaf(w1, v1.x, fmaf(w2, v2.x, fmaf(w3, v3.x, acc.x))));
            acc.y = fmaf(w0, v0.y, fmaf(w1, v1.y, fmaf(w2, v2.y, fmaf(w3, v3.y, acc.y))));
            acc.z = fmaf(w0, v0.z, fmaf(w1, v1.z, fmaf(w2, v2.z, fmaf(w3, v3.z, acc.z))));
            acc.w = fmaf(w0, v0.w, fmaf(w1, v1.w, fmaf(w2, v2.w, fmaf(w3, v3.w, acc.w))));
        }
        for (; j < m; j++) {
            int s = __shfl_sync(0xffffffffu, mm.x, j);
            float w = __int_as_float(__shfl_sync(0xffffffffu, mm.y, j));
            float4 v = ldg_h4(H, s, lane);
            acc.x = fmaf(w, v.x, acc.x); acc.y = fmaf(w, v.y, acc.y);
            acc.z = fmaf(w, v.z, acc.z); acc.w = fmaf(w, v.w, acc.w);
        }
    }
    float ds = dis[d];
    return make_float4(fmaf(ds, acc.x, bv.x), fmaf(ds, acc.y, bv.y),
                       fmaf(ds, acc.z, bv.z), fmaf(ds, acc.w, bv.w));
}

// layer-1 aggregation, one graph, warp per node -> fp16 X
__global__ __launch_bounds__(256) void k_agg1g(
    const __half* __restrict__ H, __half* __restrict__ X,
    const float* __restrict__ bias,
    const int* __restrict__ rp, const int2* __restrict__ meta,
    const float* __restrict__ dis) {
    int d = (blockIdx.x * blockDim.x + threadIdx.x) >> 5;
    int lane = threadIdx.x & 31;
    if (d >= N_NODES) return;
    float4 bv = *(const float4*)(bias + lane * 4);
    float4 acc = agg_node(H, rp, meta, dis, d, lane, bv);
    st_h4(X, d, lane, acc);
}

// layer-2 aggregation fused with pooling (both graphs)
__global__ __launch_bounds__(256) void k_agg2(
    const __half* __restrict__ H1, const __half* __restrict__ H2,
    const float* __restrict__ bias, const int* __restrict__ batch) {
    int d = (blockIdx.x * blockDim.x + threadIdx.x) >> 5;
    int lane = threadIdx.x & 31;
    if (d >= N_NODES) return;
    float4 bv = *(const float4*)(bias + lane * 4);
    float4 a21 = agg_node(H1, g_rp1, g_m1, g_dis1, d, lane, bv);
    float4 a22 = agg_node(H2, g_rp2, g_m2, g_dis2, d, lane, bv);

    float4 a11 = ldg_h4(g_x11, d, lane);
    float4 a12 = ldg_h4(g_x12, d, lane);
    float px = (a12.x - a11.x) * (a22.x - a21.x);
    float py = (a12.y - a11.y) * (a22.y - a21.y);
    float pz = (a12.z - a11.z) * (a22.z - a21.z);
    float pw = (a12.w - a11.w) * (a22.w - a21.w);
    int gph = batch[d];
    red_add_v4(g_sums + gph * 128 + lane * 4, px, py, pz, pw);
    if (lane == 0) atomicAdd(&g_cnt[gph], 1.0f);
}

// ---------------- final MLP (self-cleans g_sums / g_cnt) ----------------
__global__ __launch_bounds__(128) void k_mlp(
    const float* __restrict__ M1w, const float* __restrict__ M1b,
    const float* __restrict__ M2w, const float* __restrict__ M2b,
    const float* __restrict__ M3w, const float* __restrict__ M3b,
    const float* __restrict__ M4w, const float* __restrict__ M4b,
    float* __restrict__ out) {
    __shared__ float gv[128], h1s[128], h2s[64], h3s[32];
    int g = blockIdx.x;
    int t = threadIdx.x;
    float cnt = fmaxf(g_cnt[g], 1.0f);
    gv[t] = g_sums[g * 128 + t] / cnt;
    __syncthreads();
    g_sums[g * 128 + t] = 0.0f;
    if (t == 0) g_cnt[g] = 0.0f;
    float acc = M1b[t];
#pragma unroll 8
    for (int c = 0; c < 128; c++) acc += gv[c] * M1w[c * 128 + t];
    h1s[t] = acc;
    __syncthreads();
    if (t < 64) {
        acc = M2b[t];
#pragma unroll 8
        for (int c = 0; c < 128; c++) acc += h1s[c] * M2w[c * 64 + t];
        h2s[t] = acc;
    }
    __syncthreads();
    if (t < 32) {
        acc = M3b[t];
#pragma unroll 8
        for (int c = 0; c < 64; c++) acc += h2s[c] * M3w[c * 32 + t];
        h3s[t] = acc;
    }
    __syncthreads();
    if (t < 32) {
        float v = h3s[t] * M4w[t];
#pragma unroll
        for (int off = 16; off > 0; off >>= 1)
            v += __shfl_down_sync(0xffffffff, v, off);
        if (t == 0) out[g] = v + M4b[0];
    }
}

// ---------------- launch ----------------
extern "C" void kernel_launch(void* const* d_in, const int* in_sizes, int n_in,
                              void* d_out, int out_size) {
    const int*   ei1  = (const int*)d_in[0];
    const float* ew1  = (const float*)d_in[1];
    const int*   ei2  = (const int*)d_in[2];
    const float* ew2  = (const float*)d_in[3];
    const float* fm0  = (const float*)d_in[4];
    const float* fm1  = (const float*)d_in[5];
    const int*   batch = (const int*)d_in[6];
    const float* W1  = (const float*)d_in[7];
    const float* b1  = (const float*)d_in[8];
    const float* W2  = (const float*)d_in[9];
    const float* b2  = (const float*)d_in[10];
    const float* M1w = (const float*)d_in[11];
    const float* M1b = (const float*)d_in[12];
    const float* M2w = (const float*)d_in[13];
    const float* M2b = (const float*)d_in[14];
    const float* M3w = (const float*)d_in[15];
    const float* M3b = (const float*)d_in[16];
    const float* M4w = (const float*)d_in[17];
    const float* M4b = (const float*)d_in[18];
    float* out = (float*)d_out;

    void *p_h1, *p_h2, *p_x11, *p_x12;
    void *p_rp1, *p_rp2, *p_m1, *p_m2, *p_dis1, *p_dis2;
    cudaGetSymbolAddress(&p_h1, g_h1);
    cudaGetSymbolAddress(&p_h2, g_h2);
    cudaGetSymbolAddress(&p_x11, g_x11);
    cudaGetSymbolAddress(&p_x12, g_x12);
    cudaGetSymbolAddress(&p_rp1, g_rp1);
    cudaGetSymbolAddress(&p_rp2, g_rp2);
    cudaGetSymbolAddress(&p_m1, g_m1);
    cudaGetSymbolAddress(&p_m2, g_m2);
    cudaGetSymbolAddress(&p_dis1, g_dis1);
    cudaGetSymbolAddress(&p_dis2, g_dis2);
    __half* h1 = (__half*)p_h1;   __half* h2 = (__half*)p_h2;
    __half* x11 = (__half*)p_x11; __half* x12 = (__half*)p_x12;
    const float* dis1 = (const float*)p_dis1;
    const float* dis2 = (const float*)p_dis2;

    static cudaStream_t sA = nullptr, sB = nullptr;
    static cudaEvent_t eDis = nullptr, eFill = nullptr, eA = nullptr, eB = nullptr;
    if (sA == nullptr) {
        cudaStreamCreateWithFlags(&sA, cudaStreamNonBlocking);
        cudaStreamCreateWithFlags(&sB, cudaStreamNonBlocking);
        cudaEventCreateWithFlags(&eDis, cudaEventDisableTiming);
        cudaEventCreateWithFlags(&eFill, cudaEventDisableTiming);
        cudaEventCreateWithFlags(&eA, cudaEventDisableTiming);
        cudaEventCreateWithFlags(&eB, cudaEventDisableTiming);
    }

    const int TPB = 256;
    int nodeBlocks = (N_NODES + TPB - 1) / TPB;
    int edgeBlocks = (2 * E_EDGES + TPB - 1) / TPB;
    int gemmBlocks = (N_NODES + 127) / 128;
    int aggBlocks  = (N_NODES * 32 + TPB - 1) / TPB;

    // CSR head: deg -> dis (early, unblocks gemm1) -> scans -> fill
    k_deg<<<edgeBlocks, TPB>>>(ei1, ew1, ei2, ew2);
    k_dis<<<nodeBlocks, TPB>>>();
    cudaEventRecord(eDis, 0);

    cudaStreamWaitEvent(sA, eDis, 0);
    cudaStreamWaitEvent(sB, eDis, 0);
    k_gemm_tc<<<gemmBlocks, TPB, 0, sA>>>(fm0, W1, dis1, h1);
    k_gemm_tc<<<gemmBlocks, TPB, 0, sB>>>(fm1, W1, dis2, h2);

    {
        dim3 sg(SCAN_NBLK, 2);
        k_scanA<<<sg, SCAN_TPB>>>();
        k_scanB<<<1, 32>>>();
        k_scanC<<<sg, SCAN_TPB>>>();
    }
    k_fill<<<edgeBlocks, TPB>>>(ei1, ew1, ei2, ew2);
    cudaEventRecord(eFill, 0);
    cudaStreamWaitEvent(sA, eFill, 0);
    cudaStreamWaitEvent(sB, eFill, 0);

    // per-graph: agg1 then gemm2 (gemm2s overlap each other across streams)
    k_agg1g<<<aggBlocks, TPB, 0, sA>>>(h1, x11, b1, (const int*)p_rp1,
                                       (const int2*)p_m1, dis1);
    k_gemm_tc_h<<<gemmBlocks, TPB, 0, sA>>>(x11, W2, dis1, h1);
    k_agg1g<<<aggBlocks, TPB, 0, sB>>>(h2, x12, b1, (const int*)p_rp2,
                                       (const int2*)p_m2, dis2);
    k_gemm_tc_h<<<gemmBlocks, TPB, 0, sB>>>(x12, W2, dis2, h2);

    cudaEventRecord(eA, sA);
    cudaEventRecord(eB, sB);
    cudaStreamWaitEvent(0, eA, 0);
    cudaStreamWaitEvent(0, eB, 0);

    // join: layer-2 aggregation fused with pooling, then MLP
    k_agg2<<<aggBlocks, TPB>>>(h1, h2, b2, batch);
    k_mlp<<<NGRAPH, 128>>>(M1w, M1b, M2w, M2b, M3w, M3b, M4w, M4b, out);
}

// round 17
// speedup vs baseline: 1.1578x; 1.0514x over previous
#include <cuda_runtime.h>
#include <cuda_fp16.h>
#include <cstdint>

#define N_NODES 50000
#define E_EDGES 800000
#define D 128
#define NGRAPH 64

#define SCAN_TPB 256
#define SCAN_CHUNK 512
#define SCAN_NBLK ((N_NODES + SCAN_CHUNK - 1) / SCAN_CHUNK)   // 98

// ---------------- scratch (static __device__, no allocation) ----------------
// Invariant: g_dc, g_sums, g_cnt are ZERO at entry to every kernel_launch call.
__device__ __half g_h1[N_NODES * D];    // fp16 H' = dis*(A@W) buffers
__device__ __half g_h2[N_NODES * D];
__device__ __half g_x11[N_NODES * D];   // fp16 layer-1 outputs
__device__ __half g_x12[N_NODES * D];
__device__ __half g_w1h[128 * 128];     // W1 transposed [n][k], fp16
__device__ __half g_w2h[128 * 128];     // W2 transposed [n][k], fp16
__device__ float2 g_dc1[N_NODES];       // (weighted degree w/o self-loop, count)
__device__ float2 g_dc2[N_NODES];
__device__ float  g_dis1[N_NODES];
__device__ float  g_dis2[N_NODES];
__device__ int    g_rp1[N_NODES + 1];
__device__ int    g_rp2[N_NODES + 1];
__device__ int    g_cur1[N_NODES];
__device__ int    g_cur2[N_NODES];
__device__ int2   g_m1[E_EDGES];        // (src, float_bits(ew))
__device__ int2   g_m2[E_EDGES];
__device__ float  g_sums[NGRAPH * D];
__device__ float  g_cnt[NGRAPH];
__device__ int    g_bsum[2][SCAN_NBLK];

// ---------------- helpers ----------------
__device__ __forceinline__ void red_add_v4(float* p, float a, float b, float c, float d) {
    asm volatile(
        "{\n\t"
        ".reg .u64 q;\n\t"
        "cvta.to.global.u64 q, %0;\n\t"
        "red.global.add.v4.f32 [q], {%1, %2, %3, %4};\n\t"
        "}"
        :: "l"(p), "f"(a), "f"(b), "f"(c), "f"(d) : "memory");
}
__device__ __forceinline__ void red_add_v2(float2* p, float a, float b) {
    asm volatile(
        "{\n\t"
        ".reg .u64 q;\n\t"
        "cvta.to.global.u64 q, %0;\n\t"
        "red.global.add.v2.f32 [q], {%1, %2};\n\t"
        "}"
        :: "l"(p), "f"(a), "f"(b) : "memory");
}
__device__ __forceinline__ float4 ldg_h4(const __half* __restrict__ H, int row, int lane) {
    uint2 raw = __ldg((const uint2*)(H + row * 128 + lane * 4));
    __half2 p0 = *reinterpret_cast<__half2*>(&raw.x);
    __half2 p1 = *reinterpret_cast<__half2*>(&raw.y);
    float2 f0 = __half22float2(p0);
    float2 f1 = __half22float2(p1);
    return make_float4(f0.x, f0.y, f1.x, f1.y);
}
__device__ __forceinline__ void st_h4(__half* __restrict__ X, int row, int lane, float4 v) {
    __half2 h0 = __floats2half2_rn(v.x, v.y);
    __half2 h1 = __floats2half2_rn(v.z, v.w);
    uint2 raw;
    raw.x = *reinterpret_cast<uint32_t*>(&h0);
    raw.y = *reinterpret_cast<uint32_t*>(&h1);
    *(uint2*)(X + row * 128 + lane * 4) = raw;
}

// ---------------- weight pre-convert: Wt[n][k] = fp16(W[k][n]) ----------------
__global__ void k_wconv(const float* __restrict__ W1, const float* __restrict__ W2) {
    int i = blockIdx.x * blockDim.x + threadIdx.x;   // 0..32767
    if (i >= 2 * 128 * 128) return;
    const float* W = (i < 128 * 128) ? W1 : W2;
    __half* O = (i < 128 * 128) ? g_w1h : g_w2h;
    int j = i & (128 * 128 - 1);
    int n = j >> 7, k = j & 127;
    O[j] = __float2half_rn(W[k * 128 + n]);
}

// ---------------- CSR build (both graphs per kernel) ----------------

__global__ void k_deg(const int* __restrict__ ei1, const float* __restrict__ ew1,
                      const int* __restrict__ ei2, const float* __restrict__ ew2) {
    int t = blockIdx.x * blockDim.x + threadIdx.x;
    if (t < E_EDGES) {
        red_add_v2(&g_dc1[ei1[E_EDGES + t]], ew1[t], 1.0f);
    } else if (t < 2 * E_EDGES) {
        int e = t - E_EDGES;
        red_add_v2(&g_dc2[ei2[E_EDGES + e]], ew2[e], 1.0f);
    }
}

__global__ __launch_bounds__(SCAN_TPB) void k_scanA() {
    int g = blockIdx.y;
    const float2* dc = g ? g_dc2 : g_dc1;
    int base = blockIdx.x * SCAN_CHUNK;
    int t = threadIdx.x;
    __shared__ int red[SCAN_TPB];
    int s = 0;
    for (int i = t; i < SCAN_CHUNK; i += SCAN_TPB) {
        int idx = base + i;
        if (idx < N_NODES) s += (int)(dc[idx].y + 0.5f);
    }
    red[t] = s;
    __syncthreads();
    for (int off = SCAN_TPB / 2; off > 0; off >>= 1) {
        if (t < off) red[t] += red[t + off];
        __syncthreads();
    }
    if (t == 0) g_bsum[g][blockIdx.x] = red[0];
}

__global__ void k_scanB() {
    int t = threadIdx.x;
    if (t < 2) {
        int* bs = g_bsum[t];
        int run = 0;
        for (int b = 0; b < SCAN_NBLK; b++) {
            int v = bs[b];
            bs[b] = run;
            run += v;
        }
        int* rp = t ? g_rp2 : g_rp1;
        rp[N_NODES] = run;
    }
}

__global__ __launch_bounds__(SCAN_TPB) void k_scanC() {
    int g = blockIdx.y;
    float2* dc = g ? g_dc2 : g_dc1;
    int* rp = g ? g_rp2 : g_rp1;
    int* cur = g ? g_cur2 : g_cur1;
    float* dis = g ? g_dis2 : g_dis1;
    int base = blockIdx.x * SCAN_CHUNK;
    int t = threadIdx.x;

    __shared__ int cnts[SCAN_CHUNK];
    __shared__ int tsum[SCAN_TPB];

    for (int i = t; i < SCAN_CHUNK; i += SCAN_TPB) {
        int idx = base + i;
        if (idx < N_NODES) {
            float2 v = dc[idx];
            cnts[i] = (int)(v.y + 0.5f);
            dis[idx] = rsqrtf(v.x + 1.0f);     // +1 self-loop
            dc[idx] = make_float2(0.f, 0.f);   // restore zero-invariant
        } else {
            cnts[i] = 0;
        }
    }
    __syncthreads();

    const int EPT = SCAN_CHUNK / SCAN_TPB;     // 2
    int e0 = t * EPT;
    int ls = 0;
#pragma unroll
    for (int i = 0; i < EPT; i++) ls += cnts[e0 + i];
    tsum[t] = ls;
    __syncthreads();

    for (int off = 1; off < SCAN_TPB; off <<= 1) {
        int v = (t >= off) ? tsum[t - off] : 0;
        __syncthreads();
        tsum[t] += v;
        __syncthreads();
    }
    int run = g_bsum[g][blockIdx.x] + (t ? tsum[t - 1] : 0);

#pragma unroll
    for (int i = 0; i < EPT; i++) {
        int idx = base + e0 + i;
        if (idx < N_NODES) {
            rp[idx] = run;
            cur[idx] = run;
            run += cnts[e0 + i];
        }
    }
}

__global__ void k_fill(const int* __restrict__ ei1, const float* __restrict__ ew1,
                       const int* __restrict__ ei2, const float* __restrict__ ew2) {
    int t = blockIdx.x * blockDim.x + threadIdx.x;
    if (t < E_EDGES) {
        int s = ei1[t], d = ei1[E_EDGES + t];
        int pos = atomicAdd(&g_cur1[d], 1);
        g_m1[pos] = make_int2(s, __float_as_int(ew1[t]));
    } else if (t < 2 * E_EDGES) {
        int e = t - E_EDGES;
        int s = ei2[e], d = ei2[E_EDGES + e];
        int pos = atomicAdd(&g_cur2[d], 1);
        g_m2[pos] = make_int2(s, __float_as_int(ew2[e]));
    }
}

// -------- tensor-core GEMM (A fp32): C[N,128](fp16) = dis[r] * (A @ W) --------
// WtG is the pre-converted fp16 transposed weight [n][k].
__global__ __launch_bounds__(256) void k_gemm_tc(
    const float* __restrict__ A, const __half* __restrict__ WtG,
    const float* __restrict__ dis, __half* __restrict__ C) {
    __shared__ __half Wt[128][136];

    int t = threadIdx.x;
    for (int i = t; i < 2048; i += 256) {        // 2048 uint4 chunks of 8 halves
        int n = i >> 4, k8 = i & 15;
        *(uint4*)&Wt[n][k8 * 8] = *(const uint4*)(WtG + n * 128 + k8 * 8);
    }
    __syncthreads();

    int w = t >> 5;
    int lane = t & 31;
    int g = lane >> 2;
    int tq = lane & 3;
    int r0 = blockIdx.x * 128 + w * 16 + g;
    int r1 = r0 + 8;
    bool ok0 = r0 < N_NODES, ok1 = r1 < N_NODES;
    float ds0 = ok0 ? dis[r0] : 0.f;
    float ds1 = ok1 ? dis[r1] : 0.f;

    uint32_t af[8][4];
#pragma unroll
    for (int ks = 0; ks < 8; ks++) {
        int c = ks * 16 + tq * 2;
        float2 z = make_float2(0.f, 0.f);
        float2 f0 = ok0 ? *(const float2*)(A + r0 * 128 + c) : z;
        float2 f1 = ok1 ? *(const float2*)(A + r1 * 128 + c) : z;
        float2 f2 = ok0 ? *(const float2*)(A + r0 * 128 + c + 8) : z;
        float2 f3 = ok1 ? *(const float2*)(A + r1 * 128 + c + 8) : z;
        __half2 h0 = __floats2half2_rn(f0.x, f0.y);
        __half2 h1 = __floats2half2_rn(f1.x, f1.y);
        __half2 h2 = __floats2half2_rn(f2.x, f2.y);
        __half2 h3 = __floats2half2_rn(f3.x, f3.y);
        af[ks][0] = *reinterpret_cast<uint32_t*>(&h0);
        af[ks][1] = *reinterpret_cast<uint32_t*>(&h1);
        af[ks][2] = *reinterpret_cast<uint32_t*>(&h2);
        af[ks][3] = *reinterpret_cast<uint32_t*>(&h3);
    }

#pragma unroll
    for (int nt = 0; nt < 16; nt++) {
        float c0 = 0.f, c1 = 0.f, c2 = 0.f, c3 = 0.f;
        int n = nt * 8 + g;
        const __half* wrow = &Wt[n][0];
#pragma unroll
        for (int ks = 0; ks < 8; ks++) {
            uint32_t b0 = *(const uint32_t*)(wrow + ks * 16 + tq * 2);
            uint32_t b1 = *(const uint32_t*)(wrow + ks * 16 + tq * 2 + 8);
            asm volatile(
                "mma.sync.aligned.m16n8k16.row.col.f32.f16.f16.f32 "
                "{%0,%1,%2,%3}, {%4,%5,%6,%7}, {%8,%9}, {%0,%1,%2,%3};\n"
                : "+f"(c0), "+f"(c1), "+f"(c2), "+f"(c3)
                : "r"(af[ks][0]), "r"(af[ks][1]), "r"(af[ks][2]), "r"(af[ks][3]),
                  "r"(b0), "r"(b1));
        }
        int col = nt * 8 + tq * 2;
        if (ok0) {
            __half2 h = __floats2half2_rn(ds0 * c0, ds0 * c1);
            *(uint32_t*)(C + r0 * 128 + col) = *reinterpret_cast<uint32_t*>(&h);
        }
        if (ok1) {
            __half2 h = __floats2half2_rn(ds1 * c2, ds1 * c3);
            *(uint32_t*)(C + r1 * 128 + col) = *reinterpret_cast<uint32_t*>(&h);
        }
    }
}

// -------- tensor-core GEMM (A fp16): C[N,128](fp16) = dis[r] * (A @ W) --------
__global__ __launch_bounds__(256) void k_gemm_tc_h(
    const __half* __restrict__ A, const __half* __restrict__ WtG,
    const float* __restrict__ dis, __half* __restrict__ C) {
    __shared__ __half Wt[128][136];

    int t = threadIdx.x;
    for (int i = t; i < 2048; i += 256) {
        int n = i >> 4, k8 = i & 15;
        *(uint4*)&Wt[n][k8 * 8] = *(const uint4*)(WtG + n * 128 + k8 * 8);
    }
    __syncthreads();

    int w = t >> 5;
    int lane = t & 31;
    int g = lane >> 2;
    int tq = lane & 3;
    int r0 = blockIdx.x * 128 + w * 16 + g;
    int r1 = r0 + 8;
    bool ok0 = r0 < N_NODES, ok1 = r1 < N_NODES;
    float ds0 = ok0 ? dis[r0] : 0.f;
    float ds1 = ok1 ? dis[r1] : 0.f;

    uint32_t af[8][4];
#pragma unroll
    for (int ks = 0; ks < 8; ks++) {
        int c = ks * 16 + tq * 2;
        af[ks][0] = ok0 ? *(const uint32_t*)(A + r0 * 128 + c) : 0u;
        af[ks][1] = ok1 ? *(const uint32_t*)(A + r1 * 128 + c) : 0u;
        af[ks][2] = ok0 ? *(const uint32_t*)(A + r0 * 128 + c + 8) : 0u;
        af[ks][3] = ok1 ? *(const uint32_t*)(A + r1 * 128 + c + 8) : 0u;
    }

#pragma unroll
    for (int nt = 0; nt < 16; nt++) {
        float c0 = 0.f, c1 = 0.f, c2 = 0.f, c3 = 0.f;
        int n = nt * 8 + g;
        const __half* wrow = &Wt[n][0];
#pragma unroll
        for (int ks = 0; ks < 8; ks++) {
            uint32_t b0 = *(const uint32_t*)(wrow + ks * 16 + tq * 2);
            uint32_t b1 = *(const uint32_t*)(wrow + ks * 16 + tq * 2 + 8);
            asm volatile(
                "mma.sync.aligned.m16n8k16.row.col.f32.f16.f16.f32 "
                "{%0,%1,%2,%3}, {%4,%5,%6,%7}, {%8,%9}, {%0,%1,%2,%3};\n"
                : "+f"(c0), "+f"(c1), "+f"(c2), "+f"(c3)
                : "r"(af[ks][0]), "r"(af[ks][1]), "r"(af[ks][2]), "r"(af[ks][3]),
                  "r"(b0), "r"(b1));
        }
        int col = nt * 8 + tq * 2;
        if (ok0) {
            __half2 h = __floats2half2_rn(ds0 * c0, ds0 * c1);
            *(uint32_t*)(C + r0 * 128 + col) = *reinterpret_cast<uint32_t*>(&h);
        }
        if (ok1) {
            __half2 h = __floats2half2_rn(ds1 * c2, ds1 * c3);
            *(uint32_t*)(C + r1 * 128 + col) = *reinterpret_cast<uint32_t*>(&h);
        }
    }
}

// --------- aggregation body: acc = H'[d] + Σ ew·H'[s]; X = dis[d]*acc + b ------
__device__ __forceinline__ float4 agg_node(
    const __half* __restrict__ H, const int* __restrict__ rp,
    const int2* __restrict__ meta, const float* __restrict__ dis,
    int d, int lane, float4 bv) {
    int beg = rp[d], end = rp[d + 1];
    float4 acc = ldg_h4(H, d, lane);            // self-loop term H'[d]

    for (int base = beg; base < end; base += 32) {
        int2 mm = make_int2(0, 0);
        if (base + lane < end) mm = __ldg(&meta[base + lane]);
        int m = min(32, end - base);
        int j = 0;
        for (; j + 4 <= m; j += 4) {
            int s0 = __shfl_sync(0xffffffffu, mm.x, j);
            int s1 = __shfl_sync(0xffffffffu, mm.x, j + 1);
            int s2 = __shfl_sync(0xffffffffu, mm.x, j + 2);
            int s3 = __shfl_sync(0xffffffffu, mm.x, j + 3);
            float w0 = __int_as_float(__shfl_sync(0xffffffffu, mm.y, j));
            float w1 = __int_as_float(__shfl_sync(0xffffffffu, mm.y, j + 1));
            float w2 = __int_as_float(__shfl_sync(0xffffffffu, mm.y, j + 2));
            float w3 = __int_as_float(__shfl_sync(0xffffffffu, mm.y, j + 3));
            float4 v0 = ldg_h4(H, s0, lane);
            float4 v1 = ldg_h4(H, s1, lane);
            float4 v2 = ldg_h4(H, s2, lane);
            float4 v3 = ldg_h4(H, s3, lane);
            acc.x = fmaf(w0, v0.x, fmaf(w1, v1.x, fmaf(w2, v2.x, fmaf(w3, v3.x, acc.x))));
            acc.y = fmaf(w0, v0.y, fmaf(w1, v1.y, fmaf(w2, v2.y, fmaf(w3, v3.y, acc.y))));
            acc.z = fmaf(w0, v0.z, fmaf(w1, v1.z, fmaf(w2, v2.z, fmaf(w3, v3.z, acc.z))));
            acc.w = fmaf(w0, v0.w, fmaf(w1, v1.w, fmaf(w2, v2.w, fmaf(w3, v3.w, acc.w))));
        }
        for (; j < m; j++) {
            int s = __shfl_sync(0xffffffffu, mm.x, j);
            float w = __int_as_float(__shfl_sync(0xffffffffu, mm.y, j));
            float4 v = ldg_h4(H, s, lane);
            acc.x = fmaf(w, v.x, acc.x); acc.y = fmaf(w, v.y, acc.y);
            acc.z = fmaf(w, v.z, acc.z); acc.w = fmaf(w, v.w, acc.w);
        }
    }
    float ds = dis[d];
    return make_float4(fmaf(ds, acc.x, bv.x), fmaf(ds, acc.y, bv.y),
                       fmaf(ds, acc.z, bv.z), fmaf(ds, acc.w, bv.w));
}

// layer-1 aggregation, one graph, warp per node -> fp16 X
__global__ __launch_bounds__(256) void k_agg1g(
    const __half* __restrict__ H, __half* __restrict__ X,
    const float* __restrict__ bias,
    const int* __restrict__ rp, const int2* __restrict__ meta,
    const float* __restrict__ dis) {
    int d = (blockIdx.x * blockDim.x + threadIdx.x) >> 5;
    int lane = threadIdx.x & 31;
    if (d >= N_NODES) return;
    float4 bv = *(const float4*)(bias + lane * 4);
    float4 acc = agg_node(H, rp, meta, dis, d, lane, bv);
    st_h4(X, d, lane, acc);
}

// layer-2 aggregation fused with pooling (both graphs)
__global__ __launch_bounds__(256) void k_agg2(
    const __half* __restrict__ H1, const __half* __restrict__ H2,
    const float* __restrict__ bias, const int* __restrict__ batch) {
    int d = (blockIdx.x * blockDim.x + threadIdx.x) >> 5;
    int lane = threadIdx.x & 31;
    if (d >= N_NODES) return;
    float4 bv = *(const float4*)(bias + lane * 4);
    float4 a21 = agg_node(H1, g_rp1, g_m1, g_dis1, d, lane, bv);
    float4 a22 = agg_node(H2, g_rp2, g_m2, g_dis2, d, lane, bv);

    float4 a11 = ldg_h4(g_x11, d, lane);
    float4 a12 = ldg_h4(g_x12, d, lane);
    float px = (a12.x - a11.x) * (a22.x - a21.x);
    float py = (a12.y - a11.y) * (a22.y - a21.y);
    float pz = (a12.z - a11.z) * (a22.z - a21.z);
    float pw = (a12.w - a11.w) * (a22.w - a21.w);
    int gph = batch[d];
    red_add_v4(g_sums + gph * 128 + lane * 4, px, py, pz, pw);
    if (lane == 0) atomicAdd(&g_cnt[gph], 1.0f);
}

// ---------------- final MLP (self-cleans g_sums / g_cnt) ----------------
__global__ __launch_bounds__(128) void k_mlp(
    const float* __restrict__ M1w, const float* __restrict__ M1b,
    const float* __restrict__ M2w, const float* __restrict__ M2b,
    const float* __restrict__ M3w, const float* __restrict__ M3b,
    const float* __restrict__ M4w, const float* __restrict__ M4b,
    float* __restrict__ out) {
    __shared__ float gv[128], h1s[128], h2s[64], h3s[32];
    int g = blockIdx.x;
    int t = threadIdx.x;
    float cnt = fmaxf(g_cnt[g], 1.0f);
    gv[t] = g_sums[g * 128 + t] / cnt;
    __syncthreads();
    g_sums[g * 128 + t] = 0.0f;
    if (t == 0) g_cnt[g] = 0.0f;
    float acc = M1b[t];
#pragma unroll 8
    for (int c = 0; c < 128; c++) acc += gv[c] * M1w[c * 128 + t];
    h1s[t] = acc;
    __syncthreads();
    if (t < 64) {
        acc = M2b[t];
#pragma unroll 8
        for (int c = 0; c < 128; c++) acc += h1s[c] * M2w[c * 64 + t];
        h2s[t] = acc;
    }
    __syncthreads();
    if (t < 32) {
        acc = M3b[t];
#pragma unroll 8
        for (int c = 0; c < 64; c++) acc += h2s[c] * M3w[c * 32 + t];
        h3s[t] = acc;
    }
    __syncthreads();
    if (t < 32) {
        float v = h3s[t] * M4w[t];
#pragma unroll
        for (int off = 16; off > 0; off >>= 1)
            v += __shfl_down_sync(0xffffffff, v, off);
        if (t == 0) out[g] = v + M4b[0];
    }
}

// ---------------- launch (R14 topology + k_wconv head) ----------------
extern "C" void kernel_launch(void* const* d_in, const int* in_sizes, int n_in,
                              void* d_out, int out_size) {
    const int*   ei1  = (const int*)d_in[0];
    const float* ew1  = (const float*)d_in[1];
    const int*   ei2  = (const int*)d_in[2];
    const float* ew2  = (const float*)d_in[3];
    const float* fm0  = (const float*)d_in[4];
    const float* fm1  = (const float*)d_in[5];
    const int*   batch = (const int*)d_in[6];
    const float* W1  = (const float*)d_in[7];
    const float* b1  = (const float*)d_in[8];
    const float* W2  = (const float*)d_in[9];
    const float* b2  = (const float*)d_in[10];
    const float* M1w = (const float*)d_in[11];
    const float* M1b = (const float*)d_in[12];
    const float* M2w = (const float*)d_in[13];
    const float* M2b = (const float*)d_in[14];
    const float* M3w = (const float*)d_in[15];
    const float* M3b = (const float*)d_in[16];
    const float* M4w = (const float*)d_in[17];
    const float* M4b = (const float*)d_in[18];
    float* out = (float*)d_out;

    void *p_h1, *p_h2, *p_x11, *p_x12, *p_w1h, *p_w2h;
    void *p_rp1, *p_rp2, *p_m1, *p_m2, *p_dis1, *p_dis2;
    cudaGetSymbolAddress(&p_h1, g_h1);
    cudaGetSymbolAddress(&p_h2, g_h2);
    cudaGetSymbolAddress(&p_x11, g_x11);
    cudaGetSymbolAddress(&p_x12, g_x12);
    cudaGetSymbolAddress(&p_w1h, g_w1h);
    cudaGetSymbolAddress(&p_w2h, g_w2h);
    cudaGetSymbolAddress(&p_rp1, g_rp1);
    cudaGetSymbolAddress(&p_rp2, g_rp2);
    cudaGetSymbolAddress(&p_m1, g_m1);
    cudaGetSymbolAddress(&p_m2, g_m2);
    cudaGetSymbolAddress(&p_dis1, g_dis1);
    cudaGetSymbolAddress(&p_dis2, g_dis2);
    __half* h1 = (__half*)p_h1;   __half* h2 = (__half*)p_h2;
    __half* x11 = (__half*)p_x11; __half* x12 = (__half*)p_x12;
    const __half* w1h = (const __half*)p_w1h;
    const __half* w2h = (const __half*)p_w2h;
    const float* dis1 = (const float*)p_dis1;
    const float* dis2 = (const float*)p_dis2;

    static cudaStream_t sA = nullptr, sB = nullptr;
    static cudaEvent_t eScan = nullptr, eFill = nullptr, eA = nullptr, eB = nullptr;
    if (sA == nullptr) {
        cudaStreamCreateWithFlags(&sA, cudaStreamNonBlocking);
        cudaStreamCreateWithFlags(&sB, cudaStreamNonBlocking);
        cudaEventCreateWithFlags(&eScan, cudaEventDisableTiming);
        cudaEventCreateWithFlags(&eFill, cudaEventDisableTiming);
        cudaEventCreateWithFlags(&eA, cudaEventDisableTiming);
        cudaEventCreateWithFlags(&eB, cudaEventDisableTiming);
    }

    const int TPB = 256;
    int edgeBlocks = (2 * E_EDGES + TPB - 1) / TPB;
    int gemmBlocks = (N_NODES + 127) / 128;
    int aggBlocks  = (N_NODES * 32 + TPB - 1) / TPB;

    // head: weight pre-convert, then CSR deg -> scan
    k_wconv<<<128, TPB>>>(W1, W2);
    k_deg<<<edgeBlocks, TPB>>>(ei1, ew1, ei2, ew2);
    {
        dim3 sg(SCAN_NBLK, 2);
        k_scanA<<<sg, SCAN_TPB>>>();
        k_scanB<<<1, 32>>>();
        k_scanC<<<sg, SCAN_TPB>>>();
    }
    cudaEventRecord(eScan, 0);

    // gemm1 on streams (needs dis + w1h), concurrent with fill on default stream
    cudaStreamWaitEvent(sA, eScan, 0);
    cudaStreamWaitEvent(sB, eScan, 0);
    k_gemm_tc<<<gemmBlocks, TPB, 0, sA>>>(fm0, w1h, dis1, h1);
    k_gemm_tc<<<gemmBlocks, TPB, 0, sB>>>(fm1, w1h, dis2, h2);

    k_fill<<<edgeBlocks, TPB>>>(ei1, ew1, ei2, ew2);
    cudaEventRecord(eFill, 0);
    cudaStreamWaitEvent(sA, eFill, 0);
    cudaStreamWaitEvent(sB, eFill, 0);

    // per-graph: agg1 then gemm2 (gemm2s overlap each other across streams)
    k_agg1g<<<aggBlocks, TPB, 0, sA>>>(h1, x11, b1, (const int*)p_rp1,
                                       (const int2*)p_m1, dis1);
    k_gemm_tc_h<<<gemmBlocks, TPB, 0, sA>>>(x11, w2h, dis1, h1);
    k_agg1g<<<aggBlocks, TPB, 0, sB>>>(h2, x12, b1, (const int*)p_rp2,
                                       (const int2*)p_m2, dis2);
    k_gemm_tc_h<<<gemmBlocks, TPB, 0, sB>>>(x12, w2h, dis2, h2);

    cudaEventRecord(eA, sA);
    cudaEventRecord(eB, sB);
    cudaStreamWaitEvent(0, eA, 0);
    cudaStreamWaitEvent(0, eB, 0);

    // join: layer-2 aggregation fused with pooling, then MLP
    k_agg2<<<aggBlocks, TPB>>>(h1, h2, b2, batch);
    k_mlp<<<NGRAPH, 128>>>(M1w, M1b, M2w, M2b, M3w, M3b, M4w, M4b, out);
}